// round 1
// baseline (speedup 1.0000x reference)
#include <cuda_runtime.h>
#include <math.h>

// Problem constants
#define B_    4
#define HW    128
#define NTOK  16384            // HW*HW
#define C_    256
#define HEADS 8
#define DH    32
#define BN_   65536            // B_*NTOK

// ---------------- static device scratch (allocation-free) ----------------
__device__ float g_q[BN_ * C_];          // 64 MB
__device__ float g_k[BN_ * C_];          // 64 MB
__device__ float g_v[BN_ * C_];          // 64 MB
__device__ float g_t1[BN_ * C_];         // 64 MB  conv1+gelu output
__device__ float g_M[B_ * C_ * C_];      // per-batch fused attn*Wp matrix
__device__ float g_gram_part[8 * 32 * 32 * 32];   // [chunk][bh][i][j]
__device__ float g_ssq_part[8 * B_ * C_];         // [chunk][b*C+c]
__device__ float g_ssk_part[8 * B_ * C_];

// ---------------- classic 128x128x8 fp32 SGEMM tile ----------------
__device__ __forceinline__ void sgemm_tile(
    const float* __restrict__ A, const float* __restrict__ Bm,
    float* __restrict__ Cc, int row0, int col0,
    const float* __restrict__ bias, bool accumulate)
{
    __shared__ float As[8][128];
    __shared__ float Bs[8][128];
    const int t = threadIdx.x;           // 0..255
    const int trow = t >> 4;             // 0..15
    const int tcol = t & 15;             // 0..15

    float acc[8][8];
#pragma unroll
    for (int i = 0; i < 8; i++)
#pragma unroll
        for (int j = 0; j < 8; j++) acc[i][j] = 0.f;

    for (int k0 = 0; k0 < 256; k0 += 8) {
#pragma unroll
        for (int s = 0; s < 4; s++) {
            int idx = t + 256 * s;               // 0..1023
            int m = idx >> 3, k = idx & 7;
            As[k][m] = A[(size_t)(row0 + m) * 256 + k0 + k];
            int kk = idx >> 7, n = idx & 127;
            Bs[kk][n] = Bm[(size_t)(k0 + kk) * 256 + col0 + n];
        }
        __syncthreads();
#pragma unroll
        for (int k = 0; k < 8; k++) {
            float a[8], bv[8];
            const float4* ap = reinterpret_cast<const float4*>(&As[k][trow * 8]);
            const float4* bp4 = reinterpret_cast<const float4*>(&Bs[k][tcol * 8]);
            float4 a0 = ap[0], a1 = ap[1];
            float4 b0 = bp4[0], b1 = bp4[1];
            a[0]=a0.x; a[1]=a0.y; a[2]=a0.z; a[3]=a0.w;
            a[4]=a1.x; a[5]=a1.y; a[6]=a1.z; a[7]=a1.w;
            bv[0]=b0.x; bv[1]=b0.y; bv[2]=b0.z; bv[3]=b0.w;
            bv[4]=b1.x; bv[5]=b1.y; bv[6]=b1.z; bv[7]=b1.w;
#pragma unroll
            for (int i = 0; i < 8; i++)
#pragma unroll
                for (int j = 0; j < 8; j++) acc[i][j] += a[i] * bv[j];
        }
        __syncthreads();
    }

#pragma unroll
    for (int i = 0; i < 8; i++) {
        int r = row0 + trow * 8 + i;
#pragma unroll
        for (int j = 0; j < 8; j++) {
            int c = col0 + tcol * 8 + j;
            float v = acc[i][j];
            if (bias) v += bias[c];
            if (accumulate) Cc[(size_t)r * 256 + c] += v;
            else            Cc[(size_t)r * 256 + c]  = v;
        }
    }
}

// q = x@Wq, k = y@Wk, v = f@Wv   grid (2, 512, 3), 256 thr
__global__ void k_qkv(const float* __restrict__ x, const float* __restrict__ y,
                      const float* __restrict__ f, const float* __restrict__ Wq,
                      const float* __restrict__ Wk, const float* __restrict__ Wv)
{
    int z = blockIdx.z;
    const float* A = (z == 0) ? x : (z == 1) ? y : f;
    const float* W = (z == 0) ? Wq : (z == 1) ? Wk : Wv;
    float* Cc      = (z == 0) ? g_q : (z == 1) ? g_k : g_v;
    sgemm_tile(A, W, Cc, blockIdx.y * 128, blockIdx.x * 128, nullptr, false);
}

// out += v @ M[b] + bp   grid (2, 512), 256 thr  (out pre-filled by conv2)
__global__ void k_out(const float* __restrict__ bp, float* __restrict__ out)
{
    int row0 = blockIdx.y * 128;
    int b = row0 >> 14;                   // / 16384
    sgemm_tile(g_v, g_M + (size_t)b * 256 * 256, out, row0, blockIdx.x * 128, bp, true);
}

// token-axis sum-of-squares partials for q,k
// grid (8 cblk, 8 nchunk, 4 b); 256 thr = 8 n-lanes x 32 chans
__global__ void k_norms()
{
    int c0 = blockIdx.x * 32;
    int nc = blockIdx.y;
    int b  = blockIdx.z;
    int t = threadIdx.x, cl = t & 31, nl = t >> 5;
    size_t base = ((size_t)b * NTOK + (size_t)nc * 2048) * 256 + c0 + cl;
    float sq = 0.f, sk = 0.f;
    for (int n = nl; n < 2048; n += 8) {
        float qv = g_q[base + (size_t)n * 256]; sq += qv * qv;
        float kv = g_k[base + (size_t)n * 256]; sk += kv * kv;
    }
    __shared__ float shq[8][32], shk[8][32];
    shq[nl][cl] = sq; shk[nl][cl] = sk;
    __syncthreads();
    if (nl == 0) {
        float aq = 0.f, ak = 0.f;
#pragma unroll
        for (int i = 0; i < 8; i++) { aq += shq[i][cl]; ak += shk[i][cl]; }
        g_ssq_part[(nc * B_ + b) * C_ + c0 + cl] = aq;
        g_ssk_part[(nc * B_ + b) * C_ + c0 + cl] = ak;
    }
}

// partial Gram: G[bh][i][j] += sum_n k[n, h*32+i] * q[n, h*32+j]
// grid (8 nchunk, 32 bh); 256 thr; thread owns j=t&31, i in {t>>5 + 8s}
__global__ void k_gram()
{
    int bh = blockIdx.y, b = bh >> 3, h = bh & 7;
    int t = threadIdx.x, tj = t & 31, ti0 = t >> 5;
    __shared__ float ks[32][33], qs[32][33];
    float acc[4] = {0.f, 0.f, 0.f, 0.f};
    size_t base = ((size_t)b * NTOK + (size_t)blockIdx.x * 2048) * 256 + h * 32;

    for (int n0 = 0; n0 < 2048; n0 += 32) {
#pragma unroll
        for (int s = 0; s < 4; s++) {
            int idx = t + s * 256;
            int r = idx >> 5, c = idx & 31;
            qs[r][c] = g_q[base + (size_t)(n0 + r) * 256 + c];
            ks[r][c] = g_k[base + (size_t)(n0 + r) * 256 + c];
        }
        __syncthreads();
#pragma unroll 8
        for (int n = 0; n < 32; n++) {
            float qv = qs[n][tj];
#pragma unroll
            for (int s = 0; s < 4; s++) acc[s] += ks[n][ti0 + 8 * s] * qv;
        }
        __syncthreads();
    }
#pragma unroll
    for (int s = 0; s < 4; s++) {
        int i = ti0 + 8 * s;
        g_gram_part[(((size_t)blockIdx.x * 32 + bh) * 32 + i) * 32 + tj] = acc[s];
    }
}

// normalize + softmax + fold attn into Wp:  M[b][h*32+j][c] = sum_i attn[i][j]*Wp[h*32+i][c]
// grid (32 bh), 256 thr
__global__ void k_attn_m(const float* __restrict__ Wp, const float* __restrict__ rescale)
{
    int bh = blockIdx.x, b = bh >> 3, h = bh & 7;
    int t = threadIdx.x;
    __shared__ float attn[32][32];
    __shared__ float wp[32][256];
    __shared__ float nq[32], nk[32];

#pragma unroll
    for (int s = 0; s < 32; s++) {
        int idx = t + s * 256;                 // i=idx>>8 (==s), c=idx&255 (==t)
        wp[idx >> 8][idx & 255] = Wp[(size_t)(h * 32 + (idx >> 8)) * 256 + (idx & 255)];
    }
    if (t < 32) {
        float sq = 0.f, sk = 0.f;
#pragma unroll
        for (int ch = 0; ch < 8; ch++) {
            sq += g_ssq_part[(ch * B_ + b) * C_ + h * 32 + t];
            sk += g_ssk_part[(ch * B_ + b) * C_ + h * 32 + t];
        }
        nq[t] = fmaxf(sqrtf(sq), 1e-12f);
        nk[t] = fmaxf(sqrtf(sk), 1e-12f);
    }
    __syncthreads();

    float resc = rescale[h];
    int w = t >> 5, lane = t & 31;
    for (int i = w; i < 32; i += 8) {
        float g = 0.f;
#pragma unroll
        for (int ch = 0; ch < 8; ch++)
            g += g_gram_part[(((size_t)ch * 32 + bh) * 32 + i) * 32 + lane];
        float val = g / (nk[i] * nq[lane]) * resc;
        float m = val;
#pragma unroll
        for (int o = 16; o; o >>= 1) m = fmaxf(m, __shfl_xor_sync(0xffffffffu, m, o));
        float e = expf(val - m);
        float ssum = e;
#pragma unroll
        for (int o = 16; o; o >>= 1) ssum += __shfl_xor_sync(0xffffffffu, ssum, o);
        attn[i][lane] = e / ssum;
    }
    __syncthreads();

    float acc[32];
#pragma unroll
    for (int j = 0; j < 32; j++) acc[j] = 0.f;
#pragma unroll 4
    for (int i = 0; i < 32; i++) {
        float wpv = wp[i][t];
#pragma unroll
        for (int j = 0; j < 32; j++) acc[j] += attn[i][j] * wpv;
    }
#pragma unroll
    for (int j = 0; j < 32; j++)
        g_M[(size_t)b * 65536 + (size_t)(h * 32 + j) * 256 + t] = acc[j];
}

__device__ __forceinline__ float gelu_exact(float x)
{
    return 0.5f * x * (1.0f + erff(x * 0.7071067811865475f));
}

// t1 = gelu(dwconv(v, pw1))   grid (65536), 256 thr (one pixel, all channels)
__global__ void k_conv1(const float* __restrict__ pw)
{
    int c = threadIdx.x;
    int pix = blockIdx.x;
    int x = pix & 127;
    int yx = pix >> 7;
    int y = yx & 127;
    int b = yx >> 7;
    float acc = 0.f;
#pragma unroll
    for (int dy = -1; dy <= 1; dy++) {
        int yy = y + dy;
        if (yy < 0 || yy > 127) continue;
#pragma unroll
        for (int dx = -1; dx <= 1; dx++) {
            int xx = x + dx;
            if (xx < 0 || xx > 127) continue;
            acc += g_v[(((size_t)(b * 128 + yy)) * 128 + xx) * 256 + c]
                 * pw[((dy + 1) * 3 + (dx + 1)) * 256 + c];
        }
    }
    g_t1[(size_t)pix * 256 + c] = gelu_exact(acc);
}

// out = dwconv(t1, pw2)   (initializes d_out)
__global__ void k_conv2(const float* __restrict__ pw, float* __restrict__ out)
{
    int c = threadIdx.x;
    int pix = blockIdx.x;
    int x = pix & 127;
    int yx = pix >> 7;
    int y = yx & 127;
    float acc = 0.f;
    int b = yx >> 7;
#pragma unroll
    for (int dy = -1; dy <= 1; dy++) {
        int yy = y + dy;
        if (yy < 0 || yy > 127) continue;
#pragma unroll
        for (int dx = -1; dx <= 1; dx++) {
            int xx = x + dx;
            if (xx < 0 || xx > 127) continue;
            acc += g_t1[(((size_t)(b * 128 + yy)) * 128 + xx) * 256 + c]
                 * pw[((dy + 1) * 3 + (dx + 1)) * 256 + c];
        }
    }
    out[(size_t)pix * 256 + c] = acc;
}

extern "C" void kernel_launch(void* const* d_in, const int* in_sizes, int n_in,
                              void* d_out, int out_size)
{
    const float* x_in    = (const float*)d_in[0];
    const float* y_in    = (const float*)d_in[1];
    const float* f_in    = (const float*)d_in[2];
    const float* Wq      = (const float*)d_in[3];
    const float* Wk      = (const float*)d_in[4];
    const float* Wv      = (const float*)d_in[5];
    const float* rescale = (const float*)d_in[6];
    const float* Wp      = (const float*)d_in[7];
    const float* bp      = (const float*)d_in[8];
    const float* pw1     = (const float*)d_in[9];
    const float* pw2     = (const float*)d_in[10];
    float* out = (float*)d_out;

    // 1) q/k/v projections
    k_qkv<<<dim3(2, 512, 3), 256>>>(x_in, y_in, f_in, Wq, Wk, Wv);
    // 2) token-axis norms (partials, deterministic)
    k_norms<<<dim3(8, 8, B_), 256>>>();
    // 3) per-head Gram partials
    k_gram<<<dim3(8, 32), 256>>>();
    // 4) softmax + fold attention into Wp -> per-batch M
    k_attn_m<<<32, 256>>>(Wp, rescale);
    // 5) positional branch: conv1+gelu, then conv2 writes d_out
    k_conv1<<<BN_, 256>>>(pw1);
    k_conv2<<<BN_, 256>>>(pw2, out);
    // 6) out += v @ M[b] + bp
    k_out<<<dim3(2, 512), 256>>>(bp, out);
}

// round 3
// speedup vs baseline: 2.0577x; 2.0577x over previous
#include <cuda_runtime.h>
#include <math.h>
#include <stdint.h>

// Problem constants
#define B_    4
#define HW    128
#define NTOK  16384            // HW*HW
#define C_    256
#define HEADS 8
#define BN_   65536            // B_*NTOK

// ---------------- static device scratch (allocation-free) ----------------
__device__ float g_q[BN_ * C_];          // 64 MB
__device__ float g_k[BN_ * C_];          // 64 MB
__device__ float g_v[BN_ * C_];          // 64 MB
__device__ float g_t1[BN_ * C_];         // 64 MB
__device__ float g_Wt[3 * C_ * C_];      // tf32-rounded, transposed weights [N][K]
__device__ float g_Mt[B_ * C_ * C_];     // tf32-rounded, transposed fused attn*Wp [N][K]
__device__ float g_gram_part[8 * 32 * 32 * 32];
__device__ float g_ssq_part[8 * B_ * C_];
__device__ float g_ssk_part[8 * B_ * C_];

__device__ __forceinline__ uint32_t tf32u(float x) {
    uint32_t r; asm("cvt.rna.tf32.f32 %0, %1;" : "=r"(r) : "f"(x)); return r;
}
__device__ __forceinline__ float tf32f(float x) {
    return __uint_as_float(tf32u(x));
}

__device__ __forceinline__ void mma_tf32(float* c, const uint32_t* a, const uint32_t* b) {
    asm volatile(
        "mma.sync.aligned.m16n8k8.row.col.f32.tf32.tf32.f32 "
        "{%0,%1,%2,%3}, {%4,%5,%6,%7}, {%8,%9}, {%0,%1,%2,%3};"
        : "+f"(c[0]), "+f"(c[1]), "+f"(c[2]), "+f"(c[3])
        : "r"(a[0]), "r"(a[1]), "r"(a[2]), "r"(a[3]), "r"(b[0]), "r"(b[1]));
}

// =================== tf32 mma.sync GEMM ===================
// C[row0..+128][col0..+128] (+)= A[M,256] x Bt[N,256]^T  (Bt pre-rounded tf32)
// 256 threads = 8 warps (4m x 2n), warp tile 32x64, K chunk 32.
#define SPAD 36

template <bool ACC>
__device__ __forceinline__ void gemm_mma(
    const float* __restrict__ A, const float* __restrict__ Bt,
    float* __restrict__ C, int row0, int col0, const float* __restrict__ bias)
{
    __shared__ float As[128 * SPAD];
    __shared__ float Bs[128 * SPAD];

    const int t = threadIdx.x;
    const int warp = t >> 5, lane = t & 31;
    const int wm = (warp & 3) * 32;       // warp m offset
    const int wn = (warp >> 2) * 64;      // warp n offset
    const int g = lane >> 2;              // group id 0..7
    const int q = lane & 3;               // quad lane 0..3

    float acc[2][8][4];
#pragma unroll
    for (int mf = 0; mf < 2; mf++)
#pragma unroll
        for (int nf = 0; nf < 8; nf++)
#pragma unroll
            for (int r = 0; r < 4; r++) acc[mf][nf][r] = 0.f;

    const int ldr = t >> 3;               // 0..31 base row for loads
    const int ldc = (t & 7) * 4;          // float4 col offset

    for (int k0 = 0; k0 < 256; k0 += 32) {
        // stage A (tf32-round) and B (pre-rounded) tiles: 128x32 each
#pragma unroll
        for (int i = 0; i < 4; i++) {
            int r = ldr + i * 32;
            float4 va = *(const float4*)(A + (size_t)(row0 + r) * 256 + k0 + ldc);
            float4 ca;
            ca.x = tf32f(va.x); ca.y = tf32f(va.y);
            ca.z = tf32f(va.z); ca.w = tf32f(va.w);
            *(float4*)&As[r * SPAD + ldc] = ca;
            float4 vb = *(const float4*)(Bt + (size_t)(col0 + r) * 256 + k0 + ldc);
            *(float4*)&Bs[r * SPAD + ldc] = vb;
        }
        __syncthreads();

#pragma unroll
        for (int ks = 0; ks < 4; ks++) {
            const int kk = ks * 8;
            uint32_t af[2][4];
#pragma unroll
            for (int mf = 0; mf < 2; mf++) {
                int r = wm + mf * 16 + g;
                af[mf][0] = __float_as_uint(As[r * SPAD + kk + q]);
                af[mf][1] = __float_as_uint(As[(r + 8) * SPAD + kk + q]);
                af[mf][2] = __float_as_uint(As[r * SPAD + kk + q + 4]);
                af[mf][3] = __float_as_uint(As[(r + 8) * SPAD + kk + q + 4]);
            }
            uint32_t bf[8][2];
#pragma unroll
            for (int nf = 0; nf < 8; nf++) {
                int n = wn + nf * 8 + g;
                bf[nf][0] = __float_as_uint(Bs[n * SPAD + kk + q]);
                bf[nf][1] = __float_as_uint(Bs[n * SPAD + kk + q + 4]);
            }
#pragma unroll
            for (int mf = 0; mf < 2; mf++)
#pragma unroll
                for (int nf = 0; nf < 8; nf++)
                    mma_tf32(acc[mf][nf], af[mf], bf[nf]);
        }
        __syncthreads();
    }

    // epilogue
#pragma unroll
    for (int mf = 0; mf < 2; mf++) {
        int rbase = row0 + wm + mf * 16 + g;
#pragma unroll
        for (int nf = 0; nf < 8; nf++) {
            int cbase = col0 + wn + nf * 8 + q * 2;
            float2 v0 = make_float2(acc[mf][nf][0], acc[mf][nf][1]);
            float2 v1 = make_float2(acc[mf][nf][2], acc[mf][nf][3]);
            float2* p0 = (float2*)(C + (size_t)rbase * 256 + cbase);
            float2* p1 = (float2*)(C + (size_t)(rbase + 8) * 256 + cbase);
            if (ACC) {
                float2 o0 = *p0, o1 = *p1;
                float2 bb = *(const float2*)(bias + cbase);
                v0.x += o0.x + bb.x; v0.y += o0.y + bb.y;
                v1.x += o1.x + bb.x; v1.y += o1.y + bb.y;
            }
            *p0 = v0;
            *p1 = v1;
        }
    }
}

__global__ void __launch_bounds__(256) k_gemm_qkv(
    const float* __restrict__ x, const float* __restrict__ y, const float* __restrict__ f)
{
    int z = blockIdx.z;
    const float* A = (z == 0) ? x : (z == 1) ? y : f;
    const float* Bt = g_Wt + (size_t)z * 65536;
    float* C = (z == 0) ? g_q : (z == 1) ? g_k : g_v;
    gemm_mma<false>(A, Bt, C, blockIdx.y * 128, blockIdx.x * 128, nullptr);
}

__global__ void __launch_bounds__(256) k_gemm_out(
    const float* __restrict__ bp, float* __restrict__ out)
{
    int row0 = blockIdx.y * 128;
    int b = row0 >> 14;
    gemm_mma<true>(g_v, g_Mt + (size_t)b * 65536, out, row0, blockIdx.x * 128, bp);
}

// =================== weight transpose + tf32 rounding ===================
__global__ void k_wt(const float* __restrict__ Wq, const float* __restrict__ Wk,
                     const float* __restrict__ Wv)
{
    int z = blockIdx.z;
    const float* W = (z == 0) ? Wq : (z == 1) ? Wk : Wv;
    float* Wt = g_Wt + (size_t)z * 65536;
    __shared__ float tile[32][33];
    int tx = threadIdx.x, ty = threadIdx.y;
    int k0 = blockIdx.y * 32, n0 = blockIdx.x * 32;
#pragma unroll
    for (int i = 0; i < 4; i++)
        tile[ty + 8 * i][tx] = W[(size_t)(k0 + ty + 8 * i) * 256 + n0 + tx];
    __syncthreads();
#pragma unroll
    for (int i = 0; i < 4; i++)
        Wt[(size_t)(n0 + ty + 8 * i) * 256 + k0 + tx] = tf32f(tile[tx][ty + 8 * i]);
}

// =================== norms / gram / attn ===================
__global__ void k_norms()
{
    int c0 = blockIdx.x * 32;
    int nc = blockIdx.y;
    int b  = blockIdx.z;
    int t = threadIdx.x, cl = t & 31, nl = t >> 5;
    size_t base = ((size_t)b * NTOK + (size_t)nc * 2048) * 256 + c0 + cl;
    float sq = 0.f, sk = 0.f;
    for (int n = nl; n < 2048; n += 8) {
        float qv = g_q[base + (size_t)n * 256]; sq += qv * qv;
        float kv = g_k[base + (size_t)n * 256]; sk += kv * kv;
    }
    __shared__ float shq[8][32], shk[8][32];
    shq[nl][cl] = sq; shk[nl][cl] = sk;
    __syncthreads();
    if (nl == 0) {
        float aq = 0.f, ak = 0.f;
#pragma unroll
        for (int i = 0; i < 8; i++) { aq += shq[i][cl]; ak += shk[i][cl]; }
        g_ssq_part[(nc * B_ + b) * C_ + c0 + cl] = aq;
        g_ssk_part[(nc * B_ + b) * C_ + c0 + cl] = ak;
    }
}

__global__ void k_gram()
{
    int bh = blockIdx.y, b = bh >> 3, h = bh & 7;
    int t = threadIdx.x, tj = t & 31, ti0 = t >> 5;
    __shared__ float ks[32][33], qs[32][33];
    float acc[4] = {0.f, 0.f, 0.f, 0.f};
    size_t base = ((size_t)b * NTOK + (size_t)blockIdx.x * 2048) * 256 + h * 32;

    for (int n0 = 0; n0 < 2048; n0 += 32) {
#pragma unroll
        for (int s = 0; s < 4; s++) {
            int idx = t + s * 256;
            int r = idx >> 5, c = idx & 31;
            qs[r][c] = g_q[base + (size_t)(n0 + r) * 256 + c];
            ks[r][c] = g_k[base + (size_t)(n0 + r) * 256 + c];
        }
        __syncthreads();
#pragma unroll 8
        for (int n = 0; n < 32; n++) {
            float qv = qs[n][tj];
#pragma unroll
            for (int s = 0; s < 4; s++) acc[s] += ks[n][ti0 + 8 * s] * qv;
        }
        __syncthreads();
    }
#pragma unroll
    for (int s = 0; s < 4; s++) {
        int i = ti0 + 8 * s;
        g_gram_part[(((size_t)blockIdx.x * 32 + bh) * 32 + i) * 32 + tj] = acc[s];
    }
}

// softmax + fold attn into Wp -> write TRANSPOSED Mt[b][c][h*32+j] (tf32-rounded)
__global__ void k_attn_m(const float* __restrict__ Wp, const float* __restrict__ rescale)
{
    int bh = blockIdx.x, b = bh >> 3, h = bh & 7;
    int t = threadIdx.x;
    __shared__ float attn[32][32];
    __shared__ float wp[32][256];
    __shared__ float nq[32], nk[32];

#pragma unroll
    for (int s = 0; s < 32; s++) {
        int idx = t + s * 256;
        wp[idx >> 8][idx & 255] = Wp[(size_t)(h * 32 + (idx >> 8)) * 256 + (idx & 255)];
    }
    if (t < 32) {
        float sq = 0.f, sk = 0.f;
#pragma unroll
        for (int ch = 0; ch < 8; ch++) {
            sq += g_ssq_part[(ch * B_ + b) * C_ + h * 32 + t];
            sk += g_ssk_part[(ch * B_ + b) * C_ + h * 32 + t];
        }
        nq[t] = fmaxf(sqrtf(sq), 1e-12f);
        nk[t] = fmaxf(sqrtf(sk), 1e-12f);
    }
    __syncthreads();

    float resc = rescale[h];
    int w = t >> 5, lane = t & 31;
    for (int i = w; i < 32; i += 8) {
        float g = 0.f;
#pragma unroll
        for (int ch = 0; ch < 8; ch++)
            g += g_gram_part[(((size_t)ch * 32 + bh) * 32 + i) * 32 + lane];
        float val = g / (nk[i] * nq[lane]) * resc;
        float m = val;
#pragma unroll
        for (int o = 16; o; o >>= 1) m = fmaxf(m, __shfl_xor_sync(0xffffffffu, m, o));
        float e = expf(val - m);
        float ssum = e;
#pragma unroll
        for (int o = 16; o; o >>= 1) ssum += __shfl_xor_sync(0xffffffffu, ssum, o);
        attn[i][lane] = e / ssum;
    }
    __syncthreads();

    float acc[32];
#pragma unroll
    for (int j = 0; j < 32; j++) acc[j] = 0.f;
#pragma unroll 4
    for (int i = 0; i < 32; i++) {
        float wpv = wp[i][t];
#pragma unroll
        for (int j = 0; j < 32; j++) acc[j] += attn[i][j] * wpv;
    }
    // Mt[b][c=t][h*32+j] = sum_i attn[i][j] * Wp[h*32+i][c]
#pragma unroll
    for (int j = 0; j < 32; j++)
        g_Mt[((size_t)b * 256 + t) * 256 + h * 32 + j] = tf32f(acc[j]);
}

// =================== positional branch (depthwise convs) ===================
__device__ __forceinline__ float gelu_exact(float x)
{
    return 0.5f * x * (1.0f + erff(x * 0.7071067811865475f));
}

__global__ void k_conv1(const float* __restrict__ pw)
{
    int c = threadIdx.x;
    int pix = blockIdx.x;
    int x = pix & 127;
    int yx = pix >> 7;
    int y = yx & 127;
    int b = yx >> 7;
    float acc = 0.f;
#pragma unroll
    for (int dy = -1; dy <= 1; dy++) {
        int yy = y + dy;
        if (yy < 0 || yy > 127) continue;
#pragma unroll
        for (int dx = -1; dx <= 1; dx++) {
            int xx = x + dx;
            if (xx < 0 || xx > 127) continue;
            acc += g_v[(((size_t)(b * 128 + yy)) * 128 + xx) * 256 + c]
                 * pw[((dy + 1) * 3 + (dx + 1)) * 256 + c];
        }
    }
    g_t1[(size_t)pix * 256 + c] = gelu_exact(acc);
}

__global__ void k_conv2(const float* __restrict__ pw, float* __restrict__ out)
{
    int c = threadIdx.x;
    int pix = blockIdx.x;
    int x = pix & 127;
    int yx = pix >> 7;
    int y = yx & 127;
    int b = yx >> 7;
    float acc = 0.f;
#pragma unroll
    for (int dy = -1; dy <= 1; dy++) {
        int yy = y + dy;
        if (yy < 0 || yy > 127) continue;
#pragma unroll
        for (int dx = -1; dx <= 1; dx++) {
            int xx = x + dx;
            if (xx < 0 || xx > 127) continue;
            acc += g_t1[(((size_t)(b * 128 + yy)) * 128 + xx) * 256 + c]
                 * pw[((dy + 1) * 3 + (dx + 1)) * 256 + c];
        }
    }
    out[(size_t)pix * 256 + c] = acc;
}

extern "C" void kernel_launch(void* const* d_in, const int* in_sizes, int n_in,
                              void* d_out, int out_size)
{
    const float* x_in    = (const float*)d_in[0];
    const float* y_in    = (const float*)d_in[1];
    const float* f_in    = (const float*)d_in[2];
    const float* Wq      = (const float*)d_in[3];
    const float* Wk      = (const float*)d_in[4];
    const float* Wv      = (const float*)d_in[5];
    const float* rescale = (const float*)d_in[6];
    const float* Wp      = (const float*)d_in[7];
    const float* bp      = (const float*)d_in[8];
    const float* pw1     = (const float*)d_in[9];
    const float* pw2     = (const float*)d_in[10];
    float* out = (float*)d_out;

    // 0) transpose + tf32-round weights
    k_wt<<<dim3(8, 8, 3), dim3(32, 8)>>>(Wq, Wk, Wv);
    // 1) q/k/v projections (tf32 mma.sync)
    k_gemm_qkv<<<dim3(2, 512, 3), 256>>>(x_in, y_in, f_in);
    // 2) token-axis norms (partials)
    k_norms<<<dim3(8, 8, B_), 256>>>();
    // 3) per-head Gram partials
    k_gram<<<dim3(8, 32), 256>>>();
    // 4) softmax + fold attention into Wp -> per-batch Mt (transposed, tf32)
    k_attn_m<<<32, 256>>>(Wp, rescale);
    // 5) positional branch
    k_conv1<<<BN_, 256>>>(pw1);
    k_conv2<<<BN_, 256>>>(pw2, out);
    // 6) out += v @ M[b] + bp (tf32 mma.sync)
    k_gemm_out<<<dim3(2, 512), 256>>>(bp, out);
}

// round 4
// speedup vs baseline: 3.4376x; 1.6706x over previous
#include <cuda_runtime.h>
#include <math.h>
#include <stdint.h>

// Problem constants
#define B_    4
#define HW    128
#define NTOK  16384            // HW*HW
#define C_    256
#define HEADS 8
#define BN_   65536            // B_*NTOK
#define GNC   32               // gram n-chunks

// ---------------- static device scratch (allocation-free) ----------------
__device__ float g_q[BN_ * C_];          // 64 MB
__device__ float g_k[BN_ * C_];          // 64 MB
__device__ float g_v[BN_ * C_];          // 64 MB
__device__ float g_Wt[3 * C_ * C_];      // tf32-rounded, transposed weights [N][K]
__device__ float g_Mt[B_ * C_ * C_];     // tf32-rounded, transposed fused attn*Wp [N][K]
__device__ float g_gram_part[GNC * 32 * 32 * 32];   // 4 MB
__device__ float g_ssq_part[GNC * B_ * C_];
__device__ float g_ssk_part[GNC * B_ * C_];

__device__ __forceinline__ uint32_t tf32u(float x) {
    uint32_t r; asm("cvt.rna.tf32.f32 %0, %1;" : "=r"(r) : "f"(x)); return r;
}
__device__ __forceinline__ float tf32f(float x) {
    return __uint_as_float(tf32u(x));
}

__device__ __forceinline__ void mma_tf32(float* c, const uint32_t* a, const uint32_t* b) {
    asm volatile(
        "mma.sync.aligned.m16n8k8.row.col.f32.tf32.tf32.f32 "
        "{%0,%1,%2,%3}, {%4,%5,%6,%7}, {%8,%9}, {%0,%1,%2,%3};"
        : "+f"(c[0]), "+f"(c[1]), "+f"(c[2]), "+f"(c[3])
        : "r"(a[0]), "r"(a[1]), "r"(a[2]), "r"(a[3]), "r"(b[0]), "r"(b[1]));
}

__device__ __forceinline__ void cp16(float* s, const float* g) {
    uint32_t sa = (uint32_t)__cvta_generic_to_shared(s);
    asm volatile("cp.async.cg.shared.global [%0], [%1], 16;" :: "r"(sa), "l"(g));
}
#define CP_COMMIT() asm volatile("cp.async.commit_group;" ::: "memory")
#define CP_WAIT0()  asm volatile("cp.async.wait_group 0;" ::: "memory")

// =================== tf32 mma.sync GEMM, cp.async pipelined ===================
// C[row0..+128][col0..+128] (+)= A[M,256] x Bt[N,256]^T  (Bt pre-rounded tf32)
// 256 threads = 8 warps (4m x 2n), warp tile 32x64, K chunk 16, 2-stage pipeline.
#define KC  16
#define SP2 20

template <bool ACC>
__device__ __forceinline__ void gemm_mma(
    const float* __restrict__ A, const float* __restrict__ Bt,
    float* __restrict__ C, int row0, int col0, const float* __restrict__ bias)
{
    __shared__ float As[2][128 * SP2];
    __shared__ float Bs[2][128 * SP2];

    const int t = threadIdx.x;
    const int warp = t >> 5, lane = t & 31;
    const int wm = (warp & 3) * 32;
    const int wn = (warp >> 2) * 64;
    const int g = lane >> 2;
    const int q = lane & 3;

    float acc[2][8][4];
#pragma unroll
    for (int mf = 0; mf < 2; mf++)
#pragma unroll
        for (int nf = 0; nf < 8; nf++)
#pragma unroll
            for (int r = 0; r < 4; r++) acc[mf][nf][r] = 0.f;

    const int lr = t >> 2;                // 0..63
    const int lc4 = (t & 3) * 4;          // 0,4,8,12
    const float* Ab = A + (size_t)(row0 + lr) * 256 + lc4;
    const float* Bb = Bt + (size_t)(col0 + lr) * 256 + lc4;

    // prologue: stage 0
    {
        cp16(&As[0][lr * SP2 + lc4], Ab);
        cp16(&As[0][(lr + 64) * SP2 + lc4], Ab + 64 * 256);
        cp16(&Bs[0][lr * SP2 + lc4], Bb);
        cp16(&Bs[0][(lr + 64) * SP2 + lc4], Bb + 64 * 256);
        CP_COMMIT();
    }

    for (int c = 0; c < 16; c++) {
        const int st = c & 1;
        CP_WAIT0();
        __syncthreads();
        if (c < 15) {
            const int ns = st ^ 1;
            const float* ap = Ab + (c + 1) * KC;
            const float* bp = Bb + (c + 1) * KC;
            cp16(&As[ns][lr * SP2 + lc4], ap);
            cp16(&As[ns][(lr + 64) * SP2 + lc4], ap + 64 * 256);
            cp16(&Bs[ns][lr * SP2 + lc4], bp);
            cp16(&Bs[ns][(lr + 64) * SP2 + lc4], bp + 64 * 256);
            CP_COMMIT();
        }
#pragma unroll
        for (int ks = 0; ks < 2; ks++) {
            const int kk = ks * 8;
            uint32_t af[2][4];
#pragma unroll
            for (int mf = 0; mf < 2; mf++) {
                int r = wm + mf * 16 + g;
                af[mf][0] = tf32u(As[st][r * SP2 + kk + q]);
                af[mf][1] = tf32u(As[st][(r + 8) * SP2 + kk + q]);
                af[mf][2] = tf32u(As[st][r * SP2 + kk + q + 4]);
                af[mf][3] = tf32u(As[st][(r + 8) * SP2 + kk + q + 4]);
            }
            uint32_t bf[8][2];
#pragma unroll
            for (int nf = 0; nf < 8; nf++) {
                int n = wn + nf * 8 + g;
                bf[nf][0] = __float_as_uint(Bs[st][n * SP2 + kk + q]);
                bf[nf][1] = __float_as_uint(Bs[st][n * SP2 + kk + q + 4]);
            }
#pragma unroll
            for (int mf = 0; mf < 2; mf++)
#pragma unroll
                for (int nf = 0; nf < 8; nf++)
                    mma_tf32(acc[mf][nf], af[mf], bf[nf]);
        }
    }

    // epilogue
#pragma unroll
    for (int mf = 0; mf < 2; mf++) {
        int rbase = row0 + wm + mf * 16 + g;
#pragma unroll
        for (int nf = 0; nf < 8; nf++) {
            int cbase = col0 + wn + nf * 8 + q * 2;
            float2 v0 = make_float2(acc[mf][nf][0], acc[mf][nf][1]);
            float2 v1 = make_float2(acc[mf][nf][2], acc[mf][nf][3]);
            float2* p0 = (float2*)(C + (size_t)rbase * 256 + cbase);
            float2* p1 = (float2*)(C + (size_t)(rbase + 8) * 256 + cbase);
            if (ACC) {
                float2 o0 = *p0, o1 = *p1;
                float2 bb = *(const float2*)(bias + cbase);
                v0.x += o0.x + bb.x; v0.y += o0.y + bb.y;
                v1.x += o1.x + bb.x; v1.y += o1.y + bb.y;
            }
            *p0 = v0;
            *p1 = v1;
        }
    }
}

__global__ void __launch_bounds__(256, 2) k_gemm_qkv(
    const float* __restrict__ x, const float* __restrict__ y, const float* __restrict__ f)
{
    int z = blockIdx.z;
    const float* A = (z == 0) ? x : (z == 1) ? y : f;
    const float* Bt = g_Wt + (size_t)z * 65536;
    float* C = (z == 0) ? g_q : (z == 1) ? g_k : g_v;
    gemm_mma<false>(A, Bt, C, blockIdx.y * 128, blockIdx.x * 128, nullptr);
}

__global__ void __launch_bounds__(256, 2) k_gemm_out(
    const float* __restrict__ bp, float* __restrict__ out)
{
    int row0 = blockIdx.y * 128;
    int b = row0 >> 14;
    gemm_mma<true>(g_v, g_Mt + (size_t)b * 65536, out, row0, blockIdx.x * 128, bp);
}

// =================== weight transpose + tf32 rounding ===================
__global__ void k_wt(const float* __restrict__ Wq, const float* __restrict__ Wk,
                     const float* __restrict__ Wv)
{
    int z = blockIdx.z;
    const float* W = (z == 0) ? Wq : (z == 1) ? Wk : Wv;
    float* Wt = g_Wt + (size_t)z * 65536;
    __shared__ float tile[32][33];
    int tx = threadIdx.x, ty = threadIdx.y;
    int k0 = blockIdx.y * 32, n0 = blockIdx.x * 32;
#pragma unroll
    for (int i = 0; i < 4; i++)
        tile[ty + 8 * i][tx] = W[(size_t)(k0 + ty + 8 * i) * 256 + n0 + tx];
    __syncthreads();
#pragma unroll
    for (int i = 0; i < 4; i++)
        Wt[(size_t)(n0 + ty + 8 * i) * 256 + k0 + tx] = tf32f(tile[tx][ty + 8 * i]);
}

// =================== gram + fused token norms ===================
// grid (GNC, 32 bh), 256 thr. Each block: 512 tokens, one (b,h).
// Thread tile 4x4 via float4; 4 n-subgroups reduced at the end.
__global__ void __launch_bounds__(256) k_gram()
{
    int bh = blockIdx.y, b = bh >> 3, h = bh & 7;
    int t = threadIdx.x;
    int sub = t >> 6;                 // 0..3
    int w64 = t & 63;
    int i4 = ((w64 >> 3) & 7) * 4;    // 0..28
    int j4 = (w64 & 7) * 4;           // 0..28
    __shared__ float qs[32][36], ks[32][36];
    __shared__ float red[4][32][32];
    __shared__ float rq[8][32], rk[8][32];

    float acc[4][4];
#pragma unroll
    for (int a = 0; a < 4; a++)
#pragma unroll
        for (int d = 0; d < 4; d++) acc[a][d] = 0.f;
    float sq = 0.f, sk = 0.f;

    const int lc = t & 31, lr0 = t >> 5;
    size_t base = ((size_t)b * NTOK + (size_t)blockIdx.x * 512) * 256 + h * 32 + lc;

    for (int n0 = 0; n0 < 512; n0 += 32) {
#pragma unroll
        for (int s = 0; s < 4; s++) {
            int r = lr0 + 8 * s;
            float qv = g_q[base + (size_t)(n0 + r) * 256];
            float kv = g_k[base + (size_t)(n0 + r) * 256];
            qs[r][lc] = qv; ks[r][lc] = kv;
            sq += qv * qv; sk += kv * kv;
        }
        __syncthreads();
#pragma unroll
        for (int nn = 0; nn < 8; nn++) {
            int n = sub + nn * 4;
            float4 qv = *(const float4*)&qs[n][j4];
            float4 kv = *(const float4*)&ks[n][i4];
            acc[0][0] += kv.x * qv.x; acc[0][1] += kv.x * qv.y;
            acc[0][2] += kv.x * qv.z; acc[0][3] += kv.x * qv.w;
            acc[1][0] += kv.y * qv.x; acc[1][1] += kv.y * qv.y;
            acc[1][2] += kv.y * qv.z; acc[1][3] += kv.y * qv.w;
            acc[2][0] += kv.z * qv.x; acc[2][1] += kv.z * qv.y;
            acc[2][2] += kv.z * qv.z; acc[2][3] += kv.z * qv.w;
            acc[3][0] += kv.w * qv.x; acc[3][1] += kv.w * qv.y;
            acc[3][2] += kv.w * qv.z; acc[3][3] += kv.w * qv.w;
        }
        __syncthreads();
    }

#pragma unroll
    for (int di = 0; di < 4; di++)
#pragma unroll
        for (int dj = 0; dj < 4; dj++)
            red[sub][i4 + di][j4 + dj] = acc[di][dj];
    rq[lr0][lc] = sq;
    rk[lr0][lc] = sk;
    __syncthreads();

#pragma unroll
    for (int e = t; e < 1024; e += 256) {
        int i = e >> 5, j = e & 31;
        g_gram_part[(((size_t)blockIdx.x * 32 + bh) * 32 + i) * 32 + j]
            = red[0][i][j] + red[1][i][j] + red[2][i][j] + red[3][i][j];
    }
    if (t < 32) {
        float aq = 0.f, ak = 0.f;
#pragma unroll
        for (int i = 0; i < 8; i++) { aq += rq[i][t]; ak += rk[i][t]; }
        g_ssq_part[((size_t)blockIdx.x * B_ + b) * C_ + h * 32 + t] = aq;
        g_ssk_part[((size_t)blockIdx.x * B_ + b) * C_ + h * 32 + t] = ak;
    }
}

// softmax + fold attn into Wp -> write TRANSPOSED Mt[b][c][h*32+j] (tf32-rounded)
__global__ void k_attn_m(const float* __restrict__ Wp, const float* __restrict__ rescale)
{
    int bh = blockIdx.x, b = bh >> 3, h = bh & 7;
    int t = threadIdx.x;
    __shared__ float attn[32][32];
    __shared__ float wp[32][256];
    __shared__ float nq[32], nk[32];

#pragma unroll
    for (int s = 0; s < 32; s++) {
        int idx = t + s * 256;
        wp[idx >> 8][idx & 255] = Wp[(size_t)(h * 32 + (idx >> 8)) * 256 + (idx & 255)];
    }
    if (t < 32) {
        float sq = 0.f, sk = 0.f;
#pragma unroll
        for (int ch = 0; ch < GNC; ch++) {
            sq += g_ssq_part[((size_t)ch * B_ + b) * C_ + h * 32 + t];
            sk += g_ssk_part[((size_t)ch * B_ + b) * C_ + h * 32 + t];
        }
        nq[t] = fmaxf(sqrtf(sq), 1e-12f);
        nk[t] = fmaxf(sqrtf(sk), 1e-12f);
    }
    __syncthreads();

    float resc = rescale[h];
    int w = t >> 5, lane = t & 31;
    for (int i = w; i < 32; i += 8) {
        float g = 0.f;
#pragma unroll
        for (int ch = 0; ch < GNC; ch++)
            g += g_gram_part[(((size_t)ch * 32 + bh) * 32 + i) * 32 + lane];
        float val = g / (nk[i] * nq[lane]) * resc;
        float m = val;
#pragma unroll
        for (int o = 16; o; o >>= 1) m = fmaxf(m, __shfl_xor_sync(0xffffffffu, m, o));
        float e = expf(val - m);
        float ssum = e;
#pragma unroll
        for (int o = 16; o; o >>= 1) ssum += __shfl_xor_sync(0xffffffffu, ssum, o);
        attn[i][lane] = e / ssum;
    }
    __syncthreads();

    float acc[32];
#pragma unroll
    for (int j = 0; j < 32; j++) acc[j] = 0.f;
#pragma unroll 4
    for (int i = 0; i < 32; i++) {
        float wpv = wp[i][t];
#pragma unroll
        for (int j = 0; j < 32; j++) acc[j] += attn[i][j] * wpv;
    }
#pragma unroll
    for (int j = 0; j < 32; j++)
        g_Mt[((size_t)b * 256 + t) * 256 + h * 32 + j] = tf32f(acc[j]);
}

// =================== fused positional branch ===================
// out = dwconv2(gelu(dwconv1(v)))   tile 16x16 px, 16 ch; grid (64, 16, 4), 256 thr
__device__ __forceinline__ float gelu_exact(float x)
{
    return 0.5f * x * (1.0f + erff(x * 0.7071067811865475f));
}

__global__ void __launch_bounds__(256) k_conv(
    const float* __restrict__ pw1, const float* __restrict__ pw2,
    float* __restrict__ out)
{
    __shared__ float vs[20][20][16];
    __shared__ float t1[18][18][16];
    const int t = threadIdx.x;
    const int cl = t & 15;
    const int tp = t >> 4;
    const int c = (blockIdx.y << 4) + cl;
    const int tx0 = (blockIdx.x & 7) * 16, ty0 = (blockIdx.x >> 3) * 16;
    const int b = blockIdx.z;

    float w1[9], w2[9];
#pragma unroll
    for (int i = 0; i < 9; i++) {
        w1[i] = pw1[i * 256 + c];
        w2[i] = pw2[i * 256 + c];
    }

    // load v halo 20x20 (zero-padded)
    for (int p = tp; p < 400; p += 16) {
        int py = p / 20, px = p - py * 20;
        int gy = ty0 + py - 2, gx = tx0 + px - 2;
        float v = 0.f;
        if (gy >= 0 && gy < 128 && gx >= 0 && gx < 128)
            v = g_v[(((size_t)(b * 128 + gy)) * 128 + gx) * 256 + c];
        vs[py][px][cl] = v;
    }
    __syncthreads();

    // t1 18x18 (explicit zero outside image)
    for (int p = tp; p < 324; p += 16) {
        int py = p / 18, px = p - py * 18;
        float acc = 0.f;
#pragma unroll
        for (int dy = 0; dy < 3; dy++)
#pragma unroll
            for (int dx = 0; dx < 3; dx++)
                acc += vs[py + dy][px + dx][cl] * w1[dy * 3 + dx];
        int gy = ty0 + py - 1, gx = tx0 + px - 1;
        float val = (gy >= 0 && gy < 128 && gx >= 0 && gx < 128) ? gelu_exact(acc) : 0.f;
        t1[py][px][cl] = val;
    }
    __syncthreads();

    // out 16x16
    for (int p = tp; p < 256; p += 16) {
        int py = p >> 4, px = p & 15;
        float acc = 0.f;
#pragma unroll
        for (int dy = 0; dy < 3; dy++)
#pragma unroll
            for (int dx = 0; dx < 3; dx++)
                acc += t1[py + dy][px + dx][cl] * w2[dy * 3 + dx];
        out[(((size_t)(b * 128 + ty0 + py)) * 128 + tx0 + px) * 256 + c] = acc;
    }
}

extern "C" void kernel_launch(void* const* d_in, const int* in_sizes, int n_in,
                              void* d_out, int out_size)
{
    const float* x_in    = (const float*)d_in[0];
    const float* y_in    = (const float*)d_in[1];
    const float* f_in    = (const float*)d_in[2];
    const float* Wq      = (const float*)d_in[3];
    const float* Wk      = (const float*)d_in[4];
    const float* Wv      = (const float*)d_in[5];
    const float* rescale = (const float*)d_in[6];
    const float* Wp      = (const float*)d_in[7];
    const float* bp      = (const float*)d_in[8];
    const float* pw1     = (const float*)d_in[9];
    const float* pw2     = (const float*)d_in[10];
    float* out = (float*)d_out;

    // 0) transpose + tf32-round weights
    k_wt<<<dim3(8, 8, 3), dim3(32, 8)>>>(Wq, Wk, Wv);
    // 1) q/k/v projections (tf32 mma.sync, cp.async pipelined)
    k_gemm_qkv<<<dim3(2, 512, 3), 256>>>(x_in, y_in, f_in);
    // 2) per-head Gram partials + fused token norms
    k_gram<<<dim3(GNC, 32), 256>>>();
    // 3) softmax + fold attention into Wp -> per-batch Mt (transposed, tf32)
    k_attn_m<<<32, 256>>>(Wp, rescale);
    // 4) fused positional branch writes d_out
    k_conv<<<dim3(64, 16, 4), 256>>>(pw1, pw2, out);
    // 5) out += v @ M[b] + bp (tf32 mma.sync)
    k_gemm_out<<<dim3(2, 512), 256>>>(bp, out);
}

// round 6
// speedup vs baseline: 3.6104x; 1.0503x over previous
#include <cuda_runtime.h>
#include <cuda_fp16.h>
#include <math.h>
#include <stdint.h>

// Problem constants
#define B_    4
#define HW    128
#define NTOK  16384            // HW*HW
#define C_    256
#define HEADS 8
#define BN_   65536            // B_*NTOK
#define GNC   16               // gram n-chunks

// ---------------- static device scratch (allocation-free) ----------------
__device__ __half g_q[BN_ * C_];          // 32 MB
__device__ __half g_k[BN_ * C_];          // 32 MB
__device__ __half g_v[BN_ * C_];          // 32 MB
__device__ __half g_Wt[3 * C_ * C_];      // fp16 transposed weights [N][K]
__device__ __half g_Mt[B_ * C_ * C_];     // fp16 transposed fused attn*Wp [N][K]
__device__ float g_gram_part[GNC * 32 * 32 * 32];   // 2 MB
__device__ float g_ssq_part[GNC * B_ * C_];
__device__ float g_ssk_part[GNC * B_ * C_];

__device__ __forceinline__ void mma_f16(float* c, const uint32_t* a, const uint32_t* b) {
    asm volatile(
        "mma.sync.aligned.m16n8k16.row.col.f32.f16.f16.f32 "
        "{%0,%1,%2,%3}, {%4,%5,%6,%7}, {%8,%9}, {%0,%1,%2,%3};"
        : "+f"(c[0]), "+f"(c[1]), "+f"(c[2]), "+f"(c[3])
        : "r"(a[0]), "r"(a[1]), "r"(a[2]), "r"(a[3]), "r"(b[0]), "r"(b[1]));
}

__device__ __forceinline__ void cp16(void* s, const void* g) {
    uint32_t sa = (uint32_t)__cvta_generic_to_shared(s);
    asm volatile("cp.async.cg.shared.global [%0], [%1], 16;" :: "r"(sa), "l"(g));
}
#define CP_COMMIT() asm volatile("cp.async.commit_group;" ::: "memory")
#define CP_WAIT0()  asm volatile("cp.async.wait_group 0;" ::: "memory")

// =================== fp16 mma GEMM, 128M x 256N(full) block ===================
// 256 thr = 8 warps (2m x 4n), warp tile 64x64, K chunk 16, 2-stage pipeline.
// Race-free ordering: WAIT -> sync -> issue next chunk -> compute current.
#define KC   16
#define SPH  24

// ---- QKV: A fp32 (LDG + convert), B fp16 cp.async; writes C fp16 ----
__global__ void __launch_bounds__(256) k_gemm_qkv(
    const float* __restrict__ x, const float* __restrict__ y, const float* __restrict__ f)
{
    __shared__ __half As[2][128 * SPH];
    __shared__ __half Bs[2][256 * SPH];

    const int z = blockIdx.y;
    const float* A = (z == 0) ? x : (z == 1) ? y : f;
    const __half* Bt = g_Wt + (size_t)z * 65536;
    __half* C = (z == 0) ? g_q : (z == 1) ? g_k : g_v;
    const int row0 = blockIdx.x * 128;

    const int t = threadIdx.x;
    const int warp = t >> 5, lane = t & 31;
    const int wm0 = (warp & 1) * 64;
    const int wn0 = (warp >> 1) * 64;
    const int g = lane >> 2;
    const int q = lane & 3;

    float acc[4][8][4];
#pragma unroll
    for (int mf = 0; mf < 4; mf++)
#pragma unroll
        for (int nf = 0; nf < 8; nf++)
#pragma unroll
            for (int r = 0; r < 4; r++) acc[mf][nf][r] = 0.f;

    const int ar = t >> 1;                 // A row 0..127
    const int ak = (t & 1) * 8;            // A k-offset
    const float* Ab = A + (size_t)(row0 + ar) * 256 + ak;
    const __half* Bb = Bt + (size_t)t * 256;   // B row = t

    // prologue chunk 0
    {
        float4 pa0 = *(const float4*)(Ab);
        float4 pa1 = *(const float4*)(Ab + 4);
        cp16(&Bs[0][t * SPH], Bb);
        cp16(&Bs[0][t * SPH + 8], Bb + 8);
        CP_COMMIT();
        __half2 h[4];
        h[0] = __float22half2_rn(make_float2(pa0.x, pa0.y));
        h[1] = __float22half2_rn(make_float2(pa0.z, pa0.w));
        h[2] = __float22half2_rn(make_float2(pa1.x, pa1.y));
        h[3] = __float22half2_rn(make_float2(pa1.z, pa1.w));
        *(uint4*)&As[0][ar * SPH + ak] = *(const uint4*)h;
    }

    for (int c = 0; c < 16; c++) {
        const int st = c & 1;
        CP_WAIT0();
        __syncthreads();
        if (c < 15) {
            const int k0 = (c + 1) * KC;
            float4 pa0 = *(const float4*)(Ab + k0);
            float4 pa1 = *(const float4*)(Ab + k0 + 4);
            cp16(&Bs[st ^ 1][t * SPH], Bb + k0);
            cp16(&Bs[st ^ 1][t * SPH + 8], Bb + k0 + 8);
            CP_COMMIT();
            __half2 h[4];
            h[0] = __float22half2_rn(make_float2(pa0.x, pa0.y));
            h[1] = __float22half2_rn(make_float2(pa0.z, pa0.w));
            h[2] = __float22half2_rn(make_float2(pa1.x, pa1.y));
            h[3] = __float22half2_rn(make_float2(pa1.z, pa1.w));
            *(uint4*)&As[st ^ 1][ar * SPH + ak] = *(const uint4*)h;
        }

        uint32_t bf[8][2];
#pragma unroll
        for (int nf = 0; nf < 8; nf++) {
            int n = wn0 + nf * 8 + g;
            bf[nf][0] = *(const uint32_t*)&Bs[st][n * SPH + 2 * q];
            bf[nf][1] = *(const uint32_t*)&Bs[st][n * SPH + 2 * q + 8];
        }
#pragma unroll
        for (int mf = 0; mf < 4; mf++) {
            int r = wm0 + mf * 16 + g;
            uint32_t af[4];
            af[0] = *(const uint32_t*)&As[st][r * SPH + 2 * q];
            af[1] = *(const uint32_t*)&As[st][(r + 8) * SPH + 2 * q];
            af[2] = *(const uint32_t*)&As[st][r * SPH + 2 * q + 8];
            af[3] = *(const uint32_t*)&As[st][(r + 8) * SPH + 2 * q + 8];
#pragma unroll
            for (int nf = 0; nf < 8; nf++)
                mma_f16(acc[mf][nf], af, bf[nf]);
        }
    }

    // epilogue: write fp16
#pragma unroll
    for (int mf = 0; mf < 4; mf++) {
        int rbase = row0 + wm0 + mf * 16 + g;
#pragma unroll
        for (int nf = 0; nf < 8; nf++) {
            int cb = wn0 + nf * 8 + 2 * q;
            *(__half2*)(C + (size_t)rbase * 256 + cb)
                = __float22half2_rn(make_float2(acc[mf][nf][0], acc[mf][nf][1]));
            *(__half2*)(C + (size_t)(rbase + 8) * 256 + cb)
                = __float22half2_rn(make_float2(acc[mf][nf][2], acc[mf][nf][3]));
        }
    }
}

// ---- OUT: A fp16 (g_v) + B fp16 (g_Mt), accumulate into f32 d_out + bias ----
__global__ void __launch_bounds__(256) k_gemm_out(
    const float* __restrict__ bp, float* __restrict__ out)
{
    __shared__ __half As[2][128 * SPH];
    __shared__ __half Bs[2][256 * SPH];

    const int row0 = blockIdx.x * 128;
    const int b = row0 >> 14;
    const __half* A = g_v;
    const __half* Bt = g_Mt + (size_t)b * 65536;

    const int t = threadIdx.x;
    const int warp = t >> 5, lane = t & 31;
    const int wm0 = (warp & 1) * 64;
    const int wn0 = (warp >> 1) * 64;
    const int g = lane >> 2;
    const int q = lane & 3;

    float acc[4][8][4];
#pragma unroll
    for (int mf = 0; mf < 4; mf++)
#pragma unroll
        for (int nf = 0; nf < 8; nf++)
#pragma unroll
            for (int r = 0; r < 4; r++) acc[mf][nf][r] = 0.f;

    const int ar = t >> 1;
    const int ak = (t & 1) * 8;
    const __half* Ab = A + (size_t)(row0 + ar) * 256 + ak;
    const __half* Bb = Bt + (size_t)t * 256;

    cp16(&As[0][ar * SPH + ak], Ab);
    cp16(&Bs[0][t * SPH], Bb);
    cp16(&Bs[0][t * SPH + 8], Bb + 8);
    CP_COMMIT();

    for (int c = 0; c < 16; c++) {
        const int st = c & 1;
        CP_WAIT0();
        __syncthreads();
        if (c < 15) {
            const int k0 = (c + 1) * KC;
            cp16(&As[st ^ 1][ar * SPH + ak], Ab + k0);
            cp16(&Bs[st ^ 1][t * SPH], Bb + k0);
            cp16(&Bs[st ^ 1][t * SPH + 8], Bb + k0 + 8);
            CP_COMMIT();
        }

        uint32_t bf[8][2];
#pragma unroll
        for (int nf = 0; nf < 8; nf++) {
            int n = wn0 + nf * 8 + g;
            bf[nf][0] = *(const uint32_t*)&Bs[st][n * SPH + 2 * q];
            bf[nf][1] = *(const uint32_t*)&Bs[st][n * SPH + 2 * q + 8];
        }
#pragma unroll
        for (int mf = 0; mf < 4; mf++) {
            int r = wm0 + mf * 16 + g;
            uint32_t af[4];
            af[0] = *(const uint32_t*)&As[st][r * SPH + 2 * q];
            af[1] = *(const uint32_t*)&As[st][(r + 8) * SPH + 2 * q];
            af[2] = *(const uint32_t*)&As[st][r * SPH + 2 * q + 8];
            af[3] = *(const uint32_t*)&As[st][(r + 8) * SPH + 2 * q + 8];
#pragma unroll
            for (int nf = 0; nf < 8; nf++)
                mma_f16(acc[mf][nf], af, bf[nf]);
        }
    }

#pragma unroll
    for (int mf = 0; mf < 4; mf++) {
        int rbase = row0 + wm0 + mf * 16 + g;
#pragma unroll
        for (int nf = 0; nf < 8; nf++) {
            int cb = wn0 + nf * 8 + 2 * q;
            float2 bb = *(const float2*)(bp + cb);
            float2* p0 = (float2*)(out + (size_t)rbase * 256 + cb);
            float2* p1 = (float2*)(out + (size_t)(rbase + 8) * 256 + cb);
            float2 o0 = *p0, o1 = *p1;
            o0.x += acc[mf][nf][0] + bb.x; o0.y += acc[mf][nf][1] + bb.y;
            o1.x += acc[mf][nf][2] + bb.x; o1.y += acc[mf][nf][3] + bb.y;
            *p0 = o0;
            *p1 = o1;
        }
    }
}

// =================== weight transpose + fp16 conversion ===================
__global__ void k_wt(const float* __restrict__ Wq, const float* __restrict__ Wk,
                     const float* __restrict__ Wv)
{
    int z = blockIdx.z;
    const float* W = (z == 0) ? Wq : (z == 1) ? Wk : Wv;
    __half* Wt = g_Wt + (size_t)z * 65536;
    __shared__ float tile[32][33];
    int tx = threadIdx.x, ty = threadIdx.y;
    int k0 = blockIdx.y * 32, n0 = blockIdx.x * 32;
#pragma unroll
    for (int i = 0; i < 4; i++)
        tile[ty + 8 * i][tx] = W[(size_t)(k0 + ty + 8 * i) * 256 + n0 + tx];
    __syncthreads();
#pragma unroll
    for (int i = 0; i < 4; i++)
        Wt[(size_t)(n0 + ty + 8 * i) * 256 + k0 + tx] = __float2half_rn(tile[tx][ty + 8 * i]);
}

// =================== gram + fused token norms (reads fp16 q/k) ===================
// grid (GNC, 32 bh), 256 thr. Each block: 1024 tokens, one (b,h).
__global__ void __launch_bounds__(256) k_gram()
{
    int bh = blockIdx.y, b = bh >> 3, h = bh & 7;
    int t = threadIdx.x;
    int sub = t >> 6;
    int w64 = t & 63;
    int i4 = ((w64 >> 3) & 7) * 4;
    int j4 = (w64 & 7) * 4;
    __shared__ float qs[32][36], ks[32][36];
    __shared__ float red[4][32][32];
    __shared__ float rq[8][32], rk[8][32];

    float acc[4][4];
#pragma unroll
    for (int a = 0; a < 4; a++)
#pragma unroll
        for (int d = 0; d < 4; d++) acc[a][d] = 0.f;
    float sq = 0.f, sk = 0.f;

    const int lc = t & 31, lr0 = t >> 5;
    size_t base = ((size_t)b * NTOK + (size_t)blockIdx.x * 1024) * 256 + h * 32 + lc;

    for (int n0 = 0; n0 < 1024; n0 += 32) {
#pragma unroll
        for (int s = 0; s < 4; s++) {
            int r = lr0 + 8 * s;
            float qv = __half2float(g_q[base + (size_t)(n0 + r) * 256]);
            float kv = __half2float(g_k[base + (size_t)(n0 + r) * 256]);
            qs[r][lc] = qv; ks[r][lc] = kv;
            sq += qv * qv; sk += kv * kv;
        }
        __syncthreads();
#pragma unroll
        for (int nn = 0; nn < 8; nn++) {
            int n = sub + nn * 4;
            float4 qv = *(const float4*)&qs[n][j4];
            float4 kv = *(const float4*)&ks[n][i4];
            acc[0][0] += kv.x * qv.x; acc[0][1] += kv.x * qv.y;
            acc[0][2] += kv.x * qv.z; acc[0][3] += kv.x * qv.w;
            acc[1][0] += kv.y * qv.x; acc[1][1] += kv.y * qv.y;
            acc[1][2] += kv.y * qv.z; acc[1][3] += kv.y * qv.w;
            acc[2][0] += kv.z * qv.x; acc[2][1] += kv.z * qv.y;
            acc[2][2] += kv.z * qv.z; acc[2][3] += kv.z * qv.w;
            acc[3][0] += kv.w * qv.x; acc[3][1] += kv.w * qv.y;
            acc[3][2] += kv.w * qv.z; acc[3][3] += kv.w * qv.w;
        }
        __syncthreads();
    }

#pragma unroll
    for (int di = 0; di < 4; di++)
#pragma unroll
        for (int dj = 0; dj < 4; dj++)
            red[sub][i4 + di][j4 + dj] = acc[di][dj];
    rq[lr0][lc] = sq;
    rk[lr0][lc] = sk;
    __syncthreads();

#pragma unroll
    for (int e = t; e < 1024; e += 256) {
        int i = e >> 5, j = e & 31;
        g_gram_part[(((size_t)blockIdx.x * 32 + bh) * 32 + i) * 32 + j]
            = red[0][i][j] + red[1][i][j] + red[2][i][j] + red[3][i][j];
    }
    if (t < 32) {
        float aq = 0.f, ak = 0.f;
#pragma unroll
        for (int i = 0; i < 8; i++) { aq += rq[i][t]; ak += rk[i][t]; }
        g_ssq_part[((size_t)blockIdx.x * B_ + b) * C_ + h * 32 + t] = aq;
        g_ssk_part[((size_t)blockIdx.x * B_ + b) * C_ + h * 32 + t] = ak;
    }
}

// softmax + fold attn into Wp -> write TRANSPOSED Mt[b][c][h*32+j] as fp16
__global__ void k_attn_m(const float* __restrict__ Wp, const float* __restrict__ rescale)
{
    int bh = blockIdx.x, b = bh >> 3, h = bh & 7;
    int t = threadIdx.x;
    __shared__ float attn[32][32];
    __shared__ float wp[32][256];
    __shared__ float nq[32], nk[32];

#pragma unroll
    for (int s = 0; s < 32; s++) {
        int idx = t + s * 256;
        wp[idx >> 8][idx & 255] = Wp[(size_t)(h * 32 + (idx >> 8)) * 256 + (idx & 255)];
    }
    if (t < 32) {
        float sq = 0.f, sk = 0.f;
#pragma unroll
        for (int ch = 0; ch < GNC; ch++) {
            sq += g_ssq_part[((size_t)ch * B_ + b) * C_ + h * 32 + t];
            sk += g_ssk_part[((size_t)ch * B_ + b) * C_ + h * 32 + t];
        }
        nq[t] = fmaxf(sqrtf(sq), 1e-12f);
        nk[t] = fmaxf(sqrtf(sk), 1e-12f);
    }
    __syncthreads();

    float resc = rescale[h];
    int w = t >> 5, lane = t & 31;
    for (int i = w; i < 32; i += 8) {
        float g = 0.f;
#pragma unroll
        for (int ch = 0; ch < GNC; ch++)
            g += g_gram_part[(((size_t)ch * 32 + bh) * 32 + i) * 32 + lane];
        float val = g / (nk[i] * nq[lane]) * resc;
        float m = val;
#pragma unroll
        for (int o = 16; o; o >>= 1) m = fmaxf(m, __shfl_xor_sync(0xffffffffu, m, o));
        float e = expf(val - m);
        float ssum = e;
#pragma unroll
        for (int o = 16; o; o >>= 1) ssum += __shfl_xor_sync(0xffffffffu, ssum, o);
        attn[i][lane] = e / ssum;
    }
    __syncthreads();

    float acc[32];
#pragma unroll
    for (int j = 0; j < 32; j++) acc[j] = 0.f;
#pragma unroll 4
    for (int i = 0; i < 32; i++) {
        float wpv = wp[i][t];
#pragma unroll
        for (int j = 0; j < 32; j++) acc[j] += attn[i][j] * wpv;
    }
#pragma unroll
    for (int j = 0; j < 32; j++)
        g_Mt[((size_t)b * 256 + t) * 256 + h * 32 + j] = __float2half_rn(acc[j]);
}

// =================== fused positional branch (reads fp16 v) ===================
__device__ __forceinline__ float gelu_exact(float x)
{
    return 0.5f * x * (1.0f + erff(x * 0.7071067811865475f));
}

__global__ void __launch_bounds__(256) k_conv(
    const float* __restrict__ pw1, const float* __restrict__ pw2,
    float* __restrict__ out)
{
    __shared__ float vs[20][20][16];
    __shared__ float t1[18][18][16];
    const int t = threadIdx.x;
    const int cl = t & 15;
    const int tp = t >> 4;
    const int c = (blockIdx.y << 4) + cl;
    const int tx0 = (blockIdx.x & 7) * 16, ty0 = (blockIdx.x >> 3) * 16;
    const int b = blockIdx.z;

    float w1[9], w2[9];
#pragma unroll
    for (int i = 0; i < 9; i++) {
        w1[i] = pw1[i * 256 + c];
        w2[i] = pw2[i * 256 + c];
    }

    for (int p = tp; p < 400; p += 16) {
        int py = p / 20, px = p - py * 20;
        int gy = ty0 + py - 2, gx = tx0 + px - 2;
        float v = 0.f;
        if (gy >= 0 && gy < 128 && gx >= 0 && gx < 128)
            v = __half2float(g_v[(((size_t)(b * 128 + gy)) * 128 + gx) * 256 + c]);
        vs[py][px][cl] = v;
    }
    __syncthreads();

    for (int p = tp; p < 324; p += 16) {
        int py = p / 18, px = p - py * 18;
        float acc = 0.f;
#pragma unroll
        for (int dy = 0; dy < 3; dy++)
#pragma unroll
            for (int dx = 0; dx < 3; dx++)
                acc += vs[py + dy][px + dx][cl] * w1[dy * 3 + dx];
        int gy = ty0 + py - 1, gx = tx0 + px - 1;
        float val = (gy >= 0 && gy < 128 && gx >= 0 && gx < 128) ? gelu_exact(acc) : 0.f;
        t1[py][px][cl] = val;
    }
    __syncthreads();

    for (int p = tp; p < 256; p += 16) {
        int py = p >> 4, px = p & 15;
        float acc = 0.f;
#pragma unroll
        for (int dy = 0; dy < 3; dy++)
#pragma unroll
            for (int dx = 0; dx < 3; dx++)
                acc += t1[py + dy][px + dx][cl] * w2[dy * 3 + dx];
        out[(((size_t)(b * 128 + ty0 + py)) * 128 + tx0 + px) * 256 + c] = acc;
    }
}

extern "C" void kernel_launch(void* const* d_in, const int* in_sizes, int n_in,
                              void* d_out, int out_size)
{
    const float* x_in    = (const float*)d_in[0];
    const float* y_in    = (const float*)d_in[1];
    const float* f_in    = (const float*)d_in[2];
    const float* Wq      = (const float*)d_in[3];
    const float* Wk      = (const float*)d_in[4];
    const float* Wv      = (const float*)d_in[5];
    const float* rescale = (const float*)d_in[6];
    const float* Wp      = (const float*)d_in[7];
    const float* bp      = (const float*)d_in[8];
    const float* pw1     = (const float*)d_in[9];
    const float* pw2     = (const float*)d_in[10];
    float* out = (float*)d_out;

    // 0) transpose + fp16-convert weights
    k_wt<<<dim3(8, 8, 3), dim3(32, 8)>>>(Wq, Wk, Wv);
    // 1) q/k/v projections (fp16 mma, full-N tiles)
    k_gemm_qkv<<<dim3(512, 3), 256>>>(x_in, y_in, f_in);
    // 2) per-head Gram partials + fused token norms
    k_gram<<<dim3(GNC, 32), 256>>>();
    // 3) softmax + fold attention into Wp -> per-batch Mt (fp16)
    k_attn_m<<<32, 256>>>(Wp, rescale);
    // 4) fused positional branch writes d_out
    k_conv<<<dim3(64, 16, 4), 256>>>(pw1, pw2, out);
    // 5) out += v @ M[b] + bp (fp16 mma)
    k_gemm_out<<<512, 256>>>(bp, out);
}

// round 7
// speedup vs baseline: 3.6339x; 1.0065x over previous
#include <cuda_runtime.h>
#include <cuda_fp16.h>
#include <math.h>
#include <stdint.h>

// Problem constants
#define B_    4
#define HW    128
#define NTOK  16384            // HW*HW
#define C_    256
#define HEADS 8
#define BN_   65536            // B_*NTOK
#define GNC   16               // gram n-chunks

// ---------------- static device scratch (allocation-free) ----------------
__device__ __half g_q[BN_ * C_];          // 32 MB
__device__ __half g_k[BN_ * C_];          // 32 MB
__device__ __half g_v[BN_ * C_];          // 32 MB
__device__ __half g_Wt[3 * C_ * C_];      // fp16 transposed weights [N][K]
__device__ __half g_Mt[B_ * C_ * C_];     // fp16 transposed fused attn*Wp [N][K]
__device__ float g_gram_part[GNC * 32 * 32 * 32];   // 2 MB
__device__ float g_ssq_part[GNC * B_ * C_];
__device__ float g_ssk_part[GNC * B_ * C_];

__device__ __forceinline__ void mma_f16(float* c, const uint32_t* a, const uint32_t* b) {
    asm volatile(
        "mma.sync.aligned.m16n8k16.row.col.f32.f16.f16.f32 "
        "{%0,%1,%2,%3}, {%4,%5,%6,%7}, {%8,%9}, {%0,%1,%2,%3};"
        : "+f"(c[0]), "+f"(c[1]), "+f"(c[2]), "+f"(c[3])
        : "r"(a[0]), "r"(a[1]), "r"(a[2]), "r"(a[3]), "r"(b[0]), "r"(b[1]));
}

__device__ __forceinline__ void cp16(void* s, const void* g) {
    uint32_t sa = (uint32_t)__cvta_generic_to_shared(s);
    asm volatile("cp.async.cg.shared.global [%0], [%1], 16;" :: "r"(sa), "l"(g));
}
#define CP_COMMIT() asm volatile("cp.async.commit_group;" ::: "memory")
#define CP_WAIT0()  asm volatile("cp.async.wait_group 0;" ::: "memory")

// =================== fp16 mma GEMM, 128M x 256N block, 512 threads ===================
// 16 warps (2m x 8n), warp tile 64x32, K chunk 16, 2-stage pipeline.
// Race-free ordering: WAIT -> sync -> issue next chunk -> compute current.
#define KC   16
#define SPH  24

// ---- QKV: A fp32 (LDG + convert), B fp16 cp.async; writes C fp16 ----
__global__ void __launch_bounds__(512) k_gemm_qkv(
    const float* __restrict__ x, const float* __restrict__ y, const float* __restrict__ f)
{
    __shared__ __half As[2][128 * SPH];
    __shared__ __half Bs[2][256 * SPH];

    const int z = blockIdx.y;
    const float* A = (z == 0) ? x : (z == 1) ? y : f;
    const __half* Bt = g_Wt + (size_t)z * 65536;
    __half* C = (z == 0) ? g_q : (z == 1) ? g_k : g_v;
    const int row0 = blockIdx.x * 128;

    const int t = threadIdx.x;
    const int warp = t >> 5, lane = t & 31;
    const int wm0 = (warp & 1) * 64;        // 2 m-warps
    const int wn0 = (warp >> 1) * 32;       // 8 n-warps
    const int g = lane >> 2;
    const int q = lane & 3;

    float acc[4][4][4];
#pragma unroll
    for (int mf = 0; mf < 4; mf++)
#pragma unroll
        for (int nf = 0; nf < 4; nf++)
#pragma unroll
            for (int r = 0; r < 4; r++) acc[mf][nf][r] = 0.f;

    // A loader: 512 thr x float4 = 2048 floats = 128 rows x 16 k per chunk
    const int ar = t >> 2;                  // 0..127
    const int ak = (t & 3) * 4;             // 0,4,8,12
    const float* Ab = A + (size_t)(row0 + ar) * 256 + ak;
    // B loader: 512 thr x 16B = 8KB = 256 rows x 16 halves
    const int br = t >> 1;                  // 0..255
    const int bk = (t & 1) * 8;
    const __half* Bb = Bt + (size_t)br * 256 + bk;

    // prologue chunk 0
    {
        float4 pa = *(const float4*)(Ab);
        cp16(&Bs[0][br * SPH + bk], Bb);
        CP_COMMIT();
        __half2 h[2];
        h[0] = __float22half2_rn(make_float2(pa.x, pa.y));
        h[1] = __float22half2_rn(make_float2(pa.z, pa.w));
        *(uint2*)&As[0][ar * SPH + ak] = *(const uint2*)h;
    }

    for (int c = 0; c < 16; c++) {
        const int st = c & 1;
        CP_WAIT0();
        __syncthreads();
        if (c < 15) {
            const int k0 = (c + 1) * KC;
            float4 pa = *(const float4*)(Ab + k0);
            cp16(&Bs[st ^ 1][br * SPH + bk], Bb + k0);
            CP_COMMIT();
            __half2 h[2];
            h[0] = __float22half2_rn(make_float2(pa.x, pa.y));
            h[1] = __float22half2_rn(make_float2(pa.z, pa.w));
            *(uint2*)&As[st ^ 1][ar * SPH + ak] = *(const uint2*)h;
        }

        uint32_t bf[4][2];
#pragma unroll
        for (int nf = 0; nf < 4; nf++) {
            int n = wn0 + nf * 8 + g;
            bf[nf][0] = *(const uint32_t*)&Bs[st][n * SPH + 2 * q];
            bf[nf][1] = *(const uint32_t*)&Bs[st][n * SPH + 2 * q + 8];
        }
#pragma unroll
        for (int mf = 0; mf < 4; mf++) {
            int r = wm0 + mf * 16 + g;
            uint32_t af[4];
            af[0] = *(const uint32_t*)&As[st][r * SPH + 2 * q];
            af[1] = *(const uint32_t*)&As[st][(r + 8) * SPH + 2 * q];
            af[2] = *(const uint32_t*)&As[st][r * SPH + 2 * q + 8];
            af[3] = *(const uint32_t*)&As[st][(r + 8) * SPH + 2 * q + 8];
#pragma unroll
            for (int nf = 0; nf < 4; nf++)
                mma_f16(acc[mf][nf], af, bf[nf]);
        }
    }

    // epilogue: write fp16
#pragma unroll
    for (int mf = 0; mf < 4; mf++) {
        int rbase = row0 + wm0 + mf * 16 + g;
#pragma unroll
        for (int nf = 0; nf < 4; nf++) {
            int cb = wn0 + nf * 8 + 2 * q;
            *(__half2*)(C + (size_t)rbase * 256 + cb)
                = __float22half2_rn(make_float2(acc[mf][nf][0], acc[mf][nf][1]));
            *(__half2*)(C + (size_t)(rbase + 8) * 256 + cb)
                = __float22half2_rn(make_float2(acc[mf][nf][2], acc[mf][nf][3]));
        }
    }
}

// ---- OUT: A fp16 (g_v) + B fp16 (g_Mt), accumulate into f32 d_out + bias ----
__global__ void __launch_bounds__(512) k_gemm_out(
    const float* __restrict__ bp, float* __restrict__ out)
{
    __shared__ __half As[2][128 * SPH];
    __shared__ __half Bs[2][256 * SPH];

    const int row0 = blockIdx.x * 128;
    const int b = row0 >> 14;
    const __half* A = g_v;
    const __half* Bt = g_Mt + (size_t)b * 65536;

    const int t = threadIdx.x;
    const int warp = t >> 5, lane = t & 31;
    const int wm0 = (warp & 1) * 64;
    const int wn0 = (warp >> 1) * 32;
    const int g = lane >> 2;
    const int q = lane & 3;

    float acc[4][4][4];
#pragma unroll
    for (int mf = 0; mf < 4; mf++)
#pragma unroll
        for (int nf = 0; nf < 4; nf++)
#pragma unroll
            for (int r = 0; r < 4; r++) acc[mf][nf][r] = 0.f;

    // A loader: chunk = 128 rows x 16 halves = 4KB -> threads 0..255, 16B each
    const int ar = t >> 1;                  // row for t<256
    const int ak = (t & 1) * 8;
    const __half* Ab = A + (size_t)(row0 + ar) * 256 + ak;
    // B loader: 512 thr x 16B
    const int br = t >> 1;
    const int bk = (t & 1) * 8;
    const __half* Bb = Bt + (size_t)br * 256 + bk;

    if (t < 256) cp16(&As[0][ar * SPH + ak], Ab);
    cp16(&Bs[0][br * SPH + bk], Bb);
    CP_COMMIT();

    for (int c = 0; c < 16; c++) {
        const int st = c & 1;
        CP_WAIT0();
        __syncthreads();
        if (c < 15) {
            const int k0 = (c + 1) * KC;
            if (t < 256) cp16(&As[st ^ 1][ar * SPH + ak], Ab + k0);
            cp16(&Bs[st ^ 1][br * SPH + bk], Bb + k0);
            CP_COMMIT();
        }

        uint32_t bf[4][2];
#pragma unroll
        for (int nf = 0; nf < 4; nf++) {
            int n = wn0 + nf * 8 + g;
            bf[nf][0] = *(const uint32_t*)&Bs[st][n * SPH + 2 * q];
            bf[nf][1] = *(const uint32_t*)&Bs[st][n * SPH + 2 * q + 8];
        }
#pragma unroll
        for (int mf = 0; mf < 4; mf++) {
            int r = wm0 + mf * 16 + g;
            uint32_t af[4];
            af[0] = *(const uint32_t*)&As[st][r * SPH + 2 * q];
            af[1] = *(const uint32_t*)&As[st][(r + 8) * SPH + 2 * q];
            af[2] = *(const uint32_t*)&As[st][r * SPH + 2 * q + 8];
            af[3] = *(const uint32_t*)&As[st][(r + 8) * SPH + 2 * q + 8];
#pragma unroll
            for (int nf = 0; nf < 4; nf++)
                mma_f16(acc[mf][nf], af, bf[nf]);
        }
    }

#pragma unroll
    for (int mf = 0; mf < 4; mf++) {
        int rbase = row0 + wm0 + mf * 16 + g;
#pragma unroll
        for (int nf = 0; nf < 4; nf++) {
            int cb = wn0 + nf * 8 + 2 * q;
            float2 bb = *(const float2*)(bp + cb);
            float2* p0 = (float2*)(out + (size_t)rbase * 256 + cb);
            float2* p1 = (float2*)(out + (size_t)(rbase + 8) * 256 + cb);
            float2 o0 = *p0, o1 = *p1;
            o0.x += acc[mf][nf][0] + bb.x; o0.y += acc[mf][nf][1] + bb.y;
            o1.x += acc[mf][nf][2] + bb.x; o1.y += acc[mf][nf][3] + bb.y;
            *p0 = o0;
            *p1 = o1;
        }
    }
}

// =================== weight transpose + fp16 conversion ===================
__global__ void k_wt(const float* __restrict__ Wq, const float* __restrict__ Wk,
                     const float* __restrict__ Wv)
{
    int z = blockIdx.z;
    const float* W = (z == 0) ? Wq : (z == 1) ? Wk : Wv;
    __half* Wt = g_Wt + (size_t)z * 65536;
    __shared__ float tile[32][33];
    int tx = threadIdx.x, ty = threadIdx.y;
    int k0 = blockIdx.y * 32, n0 = blockIdx.x * 32;
#pragma unroll
    for (int i = 0; i < 4; i++)
        tile[ty + 8 * i][tx] = W[(size_t)(k0 + ty + 8 * i) * 256 + n0 + tx];
    __syncthreads();
#pragma unroll
    for (int i = 0; i < 4; i++)
        Wt[(size_t)(n0 + ty + 8 * i) * 256 + k0 + tx] = __float2half_rn(tile[tx][ty + 8 * i]);
}

// =================== gram + fused token norms (reads fp16 q/k) ===================
__global__ void __launch_bounds__(256) k_gram()
{
    int bh = blockIdx.y, b = bh >> 3, h = bh & 7;
    int t = threadIdx.x;
    int sub = t >> 6;
    int w64 = t & 63;
    int i4 = ((w64 >> 3) & 7) * 4;
    int j4 = (w64 & 7) * 4;
    __shared__ float qs[32][36], ks[32][36];
    __shared__ float red[4][32][32];
    __shared__ float rq[8][32], rk[8][32];

    float acc[4][4];
#pragma unroll
    for (int a = 0; a < 4; a++)
#pragma unroll
        for (int d = 0; d < 4; d++) acc[a][d] = 0.f;
    float sq = 0.f, sk = 0.f;

    const int lc = t & 31, lr0 = t >> 5;
    size_t base = ((size_t)b * NTOK + (size_t)blockIdx.x * 1024) * 256 + h * 32 + lc;

    for (int n0 = 0; n0 < 1024; n0 += 32) {
#pragma unroll
        for (int s = 0; s < 4; s++) {
            int r = lr0 + 8 * s;
            float qv = __half2float(g_q[base + (size_t)(n0 + r) * 256]);
            float kv = __half2float(g_k[base + (size_t)(n0 + r) * 256]);
            qs[r][lc] = qv; ks[r][lc] = kv;
            sq += qv * qv; sk += kv * kv;
        }
        __syncthreads();
#pragma unroll
        for (int nn = 0; nn < 8; nn++) {
            int n = sub + nn * 4;
            float4 qv = *(const float4*)&qs[n][j4];
            float4 kv = *(const float4*)&ks[n][i4];
            acc[0][0] += kv.x * qv.x; acc[0][1] += kv.x * qv.y;
            acc[0][2] += kv.x * qv.z; acc[0][3] += kv.x * qv.w;
            acc[1][0] += kv.y * qv.x; acc[1][1] += kv.y * qv.y;
            acc[1][2] += kv.y * qv.z; acc[1][3] += kv.y * qv.w;
            acc[2][0] += kv.z * qv.x; acc[2][1] += kv.z * qv.y;
            acc[2][2] += kv.z * qv.z; acc[2][3] += kv.z * qv.w;
            acc[3][0] += kv.w * qv.x; acc[3][1] += kv.w * qv.y;
            acc[3][2] += kv.w * qv.z; acc[3][3] += kv.w * qv.w;
        }
        __syncthreads();
    }

#pragma unroll
    for (int di = 0; di < 4; di++)
#pragma unroll
        for (int dj = 0; dj < 4; dj++)
            red[sub][i4 + di][j4 + dj] = acc[di][dj];
    rq[lr0][lc] = sq;
    rk[lr0][lc] = sk;
    __syncthreads();

#pragma unroll
    for (int e = t; e < 1024; e += 256) {
        int i = e >> 5, j = e & 31;
        g_gram_part[(((size_t)blockIdx.x * 32 + bh) * 32 + i) * 32 + j]
            = red[0][i][j] + red[1][i][j] + red[2][i][j] + red[3][i][j];
    }
    if (t < 32) {
        float aq = 0.f, ak = 0.f;
#pragma unroll
        for (int i = 0; i < 8; i++) { aq += rq[i][t]; ak += rk[i][t]; }
        g_ssq_part[((size_t)blockIdx.x * B_ + b) * C_ + h * 32 + t] = aq;
        g_ssk_part[((size_t)blockIdx.x * B_ + b) * C_ + h * 32 + t] = ak;
    }
}

// softmax + fold attn into Wp -> write TRANSPOSED Mt[b][c][h*32+j] as fp16
__global__ void k_attn_m(const float* __restrict__ Wp, const float* __restrict__ rescale)
{
    int bh = blockIdx.x, b = bh >> 3, h = bh & 7;
    int t = threadIdx.x;
    __shared__ float attn[32][32];
    __shared__ float wp[32][256];
    __shared__ float nq[32], nk[32];

#pragma unroll
    for (int s = 0; s < 32; s++) {
        int idx = t + s * 256;
        wp[idx >> 8][idx & 255] = Wp[(size_t)(h * 32 + (idx >> 8)) * 256 + (idx & 255)];
    }
    if (t < 32) {
        float sq = 0.f, sk = 0.f;
#pragma unroll
        for (int ch = 0; ch < GNC; ch++) {
            sq += g_ssq_part[((size_t)ch * B_ + b) * C_ + h * 32 + t];
            sk += g_ssk_part[((size_t)ch * B_ + b) * C_ + h * 32 + t];
        }
        nq[t] = fmaxf(sqrtf(sq), 1e-12f);
        nk[t] = fmaxf(sqrtf(sk), 1e-12f);
    }
    __syncthreads();

    float resc = rescale[h];
    int w = t >> 5, lane = t & 31;
    for (int i = w; i < 32; i += 8) {
        float g = 0.f;
#pragma unroll
        for (int ch = 0; ch < GNC; ch++)
            g += g_gram_part[(((size_t)ch * 32 + bh) * 32 + i) * 32 + lane];
        float val = g / (nk[i] * nq[lane]) * resc;
        float m = val;
#pragma unroll
        for (int o = 16; o; o >>= 1) m = fmaxf(m, __shfl_xor_sync(0xffffffffu, m, o));
        float e = expf(val - m);
        float ssum = e;
#pragma unroll
        for (int o = 16; o; o >>= 1) ssum += __shfl_xor_sync(0xffffffffu, ssum, o);
        attn[i][lane] = e / ssum;
    }
    __syncthreads();

    float acc[32];
#pragma unroll
    for (int j = 0; j < 32; j++) acc[j] = 0.f;
#pragma unroll 4
    for (int i = 0; i < 32; i++) {
        float wpv = wp[i][t];
#pragma unroll
        for (int j = 0; j < 32; j++) acc[j] += attn[i][j] * wpv;
    }
#pragma unroll
    for (int j = 0; j < 32; j++)
        g_Mt[((size_t)b * 256 + t) * 256 + h * 32 + j] = __float2half_rn(acc[j]);
}

// =================== fused positional branch (reads fp16 v) ===================
__device__ __forceinline__ float gelu_exact(float x)
{
    return 0.5f * x * (1.0f + erff(x * 0.7071067811865475f));
}

__global__ void __launch_bounds__(256) k_conv(
    const float* __restrict__ pw1, const float* __restrict__ pw2,
    float* __restrict__ out)
{
    __shared__ float vs[20][20][16];
    __shared__ float t1[18][18][16];
    const int t = threadIdx.x;
    const int cl = t & 15;
    const int tp = t >> 4;
    const int c = (blockIdx.y << 4) + cl;
    const int tx0 = (blockIdx.x & 7) * 16, ty0 = (blockIdx.x >> 3) * 16;
    const int b = blockIdx.z;

    float w1[9], w2[9];
#pragma unroll
    for (int i = 0; i < 9; i++) {
        w1[i] = pw1[i * 256 + c];
        w2[i] = pw2[i * 256 + c];
    }

    for (int p = tp; p < 400; p += 16) {
        int py = p / 20, px = p - py * 20;
        int gy = ty0 + py - 2, gx = tx0 + px - 2;
        float v = 0.f;
        if (gy >= 0 && gy < 128 && gx >= 0 && gx < 128)
            v = __half2float(g_v[(((size_t)(b * 128 + gy)) * 128 + gx) * 256 + c]);
        vs[py][px][cl] = v;
    }
    __syncthreads();

    for (int p = tp; p < 324; p += 16) {
        int py = p / 18, px = p - py * 18;
        float acc = 0.f;
#pragma unroll
        for (int dy = 0; dy < 3; dy++)
#pragma unroll
            for (int dx = 0; dx < 3; dx++)
                acc += vs[py + dy][px + dx][cl] * w1[dy * 3 + dx];
        int gy = ty0 + py - 1, gx = tx0 + px - 1;
        float val = (gy >= 0 && gy < 128 && gx >= 0 && gx < 128) ? gelu_exact(acc) : 0.f;
        t1[py][px][cl] = val;
    }
    __syncthreads();

    for (int p = tp; p < 256; p += 16) {
        int py = p >> 4, px = p & 15;
        float acc = 0.f;
#pragma unroll
        for (int dy = 0; dy < 3; dy++)
#pragma unroll
            for (int dx = 0; dx < 3; dx++)
                acc += t1[py + dy][px + dx][cl] * w2[dy * 3 + dx];
        out[(((size_t)(b * 128 + ty0 + py)) * 128 + tx0 + px) * 256 + c] = acc;
    }
}

extern "C" void kernel_launch(void* const* d_in, const int* in_sizes, int n_in,
                              void* d_out, int out_size)
{
    const float* x_in    = (const float*)d_in[0];
    const float* y_in    = (const float*)d_in[1];
    const float* f_in    = (const float*)d_in[2];
    const float* Wq      = (const float*)d_in[3];
    const float* Wk      = (const float*)d_in[4];
    const float* Wv      = (const float*)d_in[5];
    const float* rescale = (const float*)d_in[6];
    const float* Wp      = (const float*)d_in[7];
    const float* bp      = (const float*)d_in[8];
    const float* pw1     = (const float*)d_in[9];
    const float* pw2     = (const float*)d_in[10];
    float* out = (float*)d_out;

    // 0) transpose + fp16-convert weights
    k_wt<<<dim3(8, 8, 3), dim3(32, 8)>>>(Wq, Wk, Wv);
    // 1) q/k/v projections (fp16 mma, full-N tiles, 512 thr)
    k_gemm_qkv<<<dim3(512, 3), 512>>>(x_in, y_in, f_in);
    // 2) per-head Gram partials + fused token norms
    k_gram<<<dim3(GNC, 32), 256>>>();
    // 3) softmax + fold attention into Wp -> per-batch Mt (fp16)
    k_attn_m<<<32, 256>>>(Wp, rescale);
    // 4) fused positional branch writes d_out
    k_conv<<<dim3(64, 16, 4), 256>>>(pw1, pw2, out);
    // 5) out += v @ M[b] + bp (fp16 mma, 512 thr)
    k_gemm_out<<<512, 512>>>(bp, out);
}